// round 14
// baseline (speedup 1.0000x reference)
#include <cuda_runtime.h>
#include <cuda_fp16.h>
#include <cuda_bf16.h>
#include <cstddef>

// ---------------------------------------------------------------------------
// DiT block, fp16 mma.sync + ldmatrix.x4 + cp.async (split K/V groups).
// Attention: 8 warps x 16 q-rows (reg pressure halved -> 16 warps/SM).
// Softmax: no running max, single EX2 (0.125*log2e folded into Wq).
// B=4, S=4096, E=384, NH=6, HD=64, FF=1536.
// ---------------------------------------------------------------------------

#define Bsz   4
#define Ssz   4096
#define Esz   384
#define NHsz  6
#define HDsz  64
#define FFsz  1536
#define ROWS  (Bsz * Ssz)          // 16384
#define QKVN  (3 * Esz)            // 1152
#define HEADSZ ((size_t)Bsz * NHsz * Ssz * HDsz)

// ---------------- scratch ----------------
__device__ float  g_mods [6 * Bsz * Esz];
__device__ __half g_wqkvh[QKVN * Esz];    // [N=1152][K=384]
__device__ __half g_woh  [Esz * Esz];
__device__ __half g_ff1h [FFsz * Esz];    // [N=1536][K=384]
__device__ __half g_ff2h [Esz * FFsz];    // [N=384][K=1536]
__device__ __half g_y1h  [ROWS * Esz];
__device__ __half g_qkv  [3 * Bsz * NHsz * Ssz * HDsz];
__device__ __half g_atth [ROWS * Esz];
__device__ float  g_y    [ROWS * Esz];
__device__ __half g_z1h  [ROWS * Esz];
__device__ __half g_hh   [ROWS * FFsz];

// ---------------- PTX helpers ----------------
__device__ __forceinline__ void mma16816(float* c, const unsigned* a, const unsigned* b)
{
    asm volatile(
        "mma.sync.aligned.m16n8k16.row.col.f32.f16.f16.f32 "
        "{%0,%1,%2,%3},{%4,%5,%6,%7},{%8,%9},{%0,%1,%2,%3};"
        : "+f"(c[0]), "+f"(c[1]), "+f"(c[2]), "+f"(c[3])
        : "r"(a[0]), "r"(a[1]), "r"(a[2]), "r"(a[3]), "r"(b[0]), "r"(b[1]));
}
__device__ __forceinline__ unsigned packh2(float a, float b)
{
    __half2 h = __floats2half2_rn(a, b);
    return *(unsigned*)&h;
}
__device__ __forceinline__ float ex2(float x)
{
    float r;
    asm("ex2.approx.f32 %0, %1;" : "=f"(r) : "f"(x));
    return r;
}
__device__ __forceinline__ unsigned sptr(const void* p)
{
    return (unsigned)__cvta_generic_to_shared(p);
}
__device__ __forceinline__ void ldmx4(unsigned* r, unsigned addr)
{
    asm volatile("ldmatrix.sync.aligned.m8n8.x4.shared.b16 {%0,%1,%2,%3},[%4];"
                 : "=r"(r[0]), "=r"(r[1]), "=r"(r[2]), "=r"(r[3]) : "r"(addr));
}
__device__ __forceinline__ void ldmx4t(unsigned* r, unsigned addr)
{
    asm volatile("ldmatrix.sync.aligned.m8n8.x4.trans.shared.b16 {%0,%1,%2,%3},[%4];"
                 : "=r"(r[0]), "=r"(r[1]), "=r"(r[2]), "=r"(r[3]) : "r"(addr));
}
__device__ __forceinline__ void cp16(unsigned dst, const void* src)
{
    asm volatile("cp.async.cg.shared.global [%0],[%1],16;" :: "r"(dst), "l"(src));
}
#define CP_COMMIT() asm volatile("cp.async.commit_group;")
#define CP_WAIT0()  asm volatile("cp.async.wait_group 0;")
#define CP_WAIT1()  asm volatile("cp.async.wait_group 1;")
#define CP_WAIT2()  asm volatile("cp.async.wait_group 2;")

// ---------------------------------------------------------------------------
// 0) merged weight convert (+ per-job scale): W[K][N] fp32 -> Wt[N][K] fp16
// ---------------------------------------------------------------------------
struct CvtJobs {
    const float* W[6];
    __half*      Wt[6];
    float scl[6];
    int K[6], N[6], b0[6];
};

__global__ __launch_bounds__(256)
void convert_all_k(CvtJobs j)
{
    __shared__ float t[32][33];
    int bid = blockIdx.x;
    int ji = 0;
    #pragma unroll
    for (int i = 1; i < 6; i++) if (bid >= j.b0[i]) ji = i;
    int tile = bid - j.b0[ji];
    int K = j.K[ji], N = j.N[ji];
    int nkt = K >> 5;
    int k0 = (tile % nkt) << 5, n0 = (tile / nkt) << 5;
    float scl = j.scl[ji];

    const float* W  = j.W[ji];
    __half*      Wt = j.Wt[ji];
    int tx = threadIdx.x & 31, ty = threadIdx.x >> 5;
    #pragma unroll
    for (int i = 0; i < 32; i += 8)
        t[ty + i][tx] = W[(size_t)(k0 + ty + i) * N + n0 + tx];
    __syncthreads();
    #pragma unroll
    for (int i = 0; i < 32; i += 8)
        Wt[(size_t)(n0 + ty + i) * K + k0 + tx] = __float2half(t[tx][ty + i] * scl);
}

// ---------------------------------------------------------------------------
// 1) cond projections
// ---------------------------------------------------------------------------
struct CondPtrs { const float* w[6]; const float* b[6]; };

__global__ __launch_bounds__(384)
void cond_proj_k(const float* __restrict__ cond, CondPtrs p, float* __restrict__ mods)
{
    __shared__ float cs[Esz];
    int n  = threadIdx.x;
    int pi = blockIdx.x;
    int b  = blockIdx.y;
    cs[n] = cond[b * Esz + n];
    __syncthreads();
    const float* W = p.w[pi];
    float acc = p.b[pi][n];
    #pragma unroll 4
    for (int k = 0; k < Esz; k++)
        acc += cs[k] * W[k * Esz + n];
    mods[(pi * Bsz + b) * Esz + n] = acc;
}

// ---------------------------------------------------------------------------
// 2) fused LayerNorm + AdaLN modulation -> fp16
// ---------------------------------------------------------------------------
__global__ __launch_bounds__(128)
void ln_mod_k(const float* __restrict__ X,
              const float* __restrict__ lw, const float* __restrict__ lb,
              const float* __restrict__ gamma, const float* __restrict__ beta,
              __half* __restrict__ Y)
{
    __shared__ float sb1[4], sb2[4];
    int row = blockIdx.x;
    int b   = row >> 12;
    const float* x = X + (size_t)row * Esz;
    int t = threadIdx.x;

    float v0 = x[t], v1 = x[t + 128], v2 = x[t + 256];
    float s = v0 + v1 + v2;
    #pragma unroll
    for (int m = 16; m >= 1; m >>= 1) s += __shfl_xor_sync(0xffffffffu, s, m);
    if ((t & 31) == 0) sb1[t >> 5] = s;
    __syncthreads();
    float mean = (sb1[0] + sb1[1] + sb1[2] + sb1[3]) * (1.0f / Esz);

    float d0 = v0 - mean, d1 = v1 - mean, d2 = v2 - mean;
    float sq = d0 * d0 + d1 * d1 + d2 * d2;
    #pragma unroll
    for (int m = 16; m >= 1; m >>= 1) sq += __shfl_xor_sync(0xffffffffu, sq, m);
    if ((t & 31) == 0) sb2[t >> 5] = sq;
    __syncthreads();
    float var  = (sb2[0] + sb2[1] + sb2[2] + sb2[3]) * (1.0f / Esz);
    float rinv = rsqrtf(var + 1e-5f);

    __half* y = Y + (size_t)row * Esz;
    const float* gm = gamma + b * Esz;
    const float* bt = beta  + b * Esz;
    #pragma unroll
    for (int c = 0; c < 3; c++) {
        int   idx = t + c * 128;
        float d   = (c == 0 ? d0 : (c == 1 ? d1 : d2));
        float ln  = d * rinv * lw[idx] + lb[idx];
        y[idx] = __float2half(ln * (1.0f + gm[idx]) + bt[idx]);
    }
}

// ---------------------------------------------------------------------------
// 3) fp16 GEMM, block 128x128, BK=32, 8 warps (4m x 2n), warp 32x64.
//    (unchanged; tcgen05 port is next)
// ---------------------------------------------------------------------------
enum { EPI_QKV = 0, EPI_WO = 1, EPI_FF1 = 2, EPI_FF2 = 3 };

template <int EPI>
__global__ __launch_bounds__(256)
void hgemm_k(const __half* __restrict__ A, const __half* __restrict__ Wt,
             const float* __restrict__ bias, void* __restrict__ Cout,
             int N, int K,
             const float* __restrict__ resid, const float* __restrict__ alpha)
{
    __shared__ __half As[2][128][40];
    __shared__ __half Ws[2][128][40];

    int tid  = threadIdx.x;
    int lane = tid & 31;
    int wid  = tid >> 5;
    int wm   = wid & 3;
    int wn   = wid >> 2;
    int bm   = blockIdx.x * 128;
    int bn   = blockIdx.y * 128;

    float acc[2][8][4] = {};

    #pragma unroll
    for (int i = 0; i < 2; i++) {
        int c = tid + i * 256;
        int row = c >> 2, ch = (c & 3) << 3;
        cp16(sptr(&As[0][row][ch]), A  + (size_t)(bm + row) * K + ch);
        cp16(sptr(&Ws[0][row][ch]), Wt + (size_t)(bn + row) * K + ch);
    }
    CP_COMMIT();

    int nit = K >> 5;
    #pragma unroll 1
    for (int it = 0; it < nit; it++) {
        CP_WAIT0();
        __syncthreads();
        if (it + 1 < nit) {
            int k0 = (it + 1) << 5;
            int nb = (it + 1) & 1;
            #pragma unroll
            for (int i = 0; i < 2; i++) {
                int c = tid + i * 256;
                int row = c >> 2, ch = (c & 3) << 3;
                cp16(sptr(&As[nb][row][ch]), A  + (size_t)(bm + row) * K + k0 + ch);
                cp16(sptr(&Ws[nb][row][ch]), Wt + (size_t)(bn + row) * K + k0 + ch);
            }
            CP_COMMIT();
        }
        int buf = it & 1;

        #pragma unroll
        for (int ks = 0; ks < 2; ks++) {
            int c0 = ks * 16;
            unsigned a[2][4], b[8][2];
            #pragma unroll
            for (int mt = 0; mt < 2; mt++)
                ldmx4(a[mt], sptr(&As[buf][wm * 32 + mt * 16 + (lane & 15)]
                                         [c0 + ((lane >> 4) << 3)]));
            #pragma unroll
            for (int ntp = 0; ntp < 4; ntp++) {
                unsigned bb[4];
                ldmx4(bb, sptr(&Ws[buf][wn * 64 + ntp * 16 + ((lane >> 4) << 3) + (lane & 7)]
                                       [c0 + (((lane >> 3) & 1) << 3)]));
                b[2 * ntp][0]     = bb[0]; b[2 * ntp][1]     = bb[1];
                b[2 * ntp + 1][0] = bb[2]; b[2 * ntp + 1][1] = bb[3];
            }
            #pragma unroll
            for (int mt = 0; mt < 2; mt++)
                #pragma unroll
                for (int nt = 0; nt < 8; nt++)
                    mma16816(acc[mt][nt], a[mt], b[nt]);
        }
    }

    // ---- epilogue ----
    #pragma unroll
    for (int mt = 0; mt < 2; mt++) {
        int r = bm + wm * 32 + mt * 16 + (lane >> 2);
        #pragma unroll
        for (int nt = 0; nt < 8; nt++) {
            int c = bn + wn * 64 + nt * 8 + ((lane & 3) << 1);
            float* ac = acc[mt][nt];

            if (EPI == EPI_QKV) {
                __half* C = (__half*)Cout;
                int which = c / Esz, cc = c % Esz;
                int h = cc >> 6, d = cc & 63;
                #pragma unroll
                for (int rr = 0; rr < 2; rr++) {
                    int m = r + rr * 8, b = m >> 12, s = m & 4095;
                    __half2 v = __floats2half2_rn(ac[rr * 2], ac[rr * 2 + 1]);
                    size_t idx = ((((size_t)which * Bsz + b) * NHsz + h) * Ssz + s);
                    *(__half2*)&C[(idx << 6) + d] = v;
                }
            } else if (EPI == EPI_FF1) {
                __half* C = (__half*)Cout;
                float b0 = bias[c], b1 = bias[c + 1];
                #pragma unroll
                for (int rr = 0; rr < 2; rr++) {
                    int m = r + rr * 8;
                    float t0 = ac[rr * 2] + b0;     t0 = t0 > 0.f ? t0 : 0.f;
                    float t1 = ac[rr * 2 + 1] + b1; t1 = t1 > 0.f ? t1 : 0.f;
                    *(__half2*)&C[(size_t)m * N + c] = __floats2half2_rn(t0, t1);
                }
            } else {
                float* C = (float*)Cout;
                float b0 = 0.f, b1 = 0.f;
                if (EPI == EPI_FF2) { b0 = bias[c]; b1 = bias[c + 1]; }
                #pragma unroll
                for (int rr = 0; rr < 2; rr++) {
                    int m = r + rr * 8, bb = m >> 12;
                    float2 al = *(const float2*)&alpha[bb * Esz + c];
                    float2 rs = *(const float2*)&resid[(size_t)m * Esz + c];
                    float2 v;
                    v.x = rs.x + (ac[rr * 2] + b0) * al.x;
                    v.y = rs.y + (ac[rr * 2 + 1] + b1) * al.y;
                    *(float2*)&C[(size_t)m * Esz + c] = v;
                }
            }
        }
    }
}

// ---------------------------------------------------------------------------
// 4) fp16 flash attention: 256 threads, 8 warps x 16 q-rows (Q tile 128),
//    KV tile 64, split cp.async groups, EX2 softmax, in-place P pack.
// ---------------------------------------------------------------------------
#define ASTR 72

union PU { float f[8][4]; unsigned u[32]; };

__global__ __launch_bounds__(256, 2)
void attn_h_k(const __half* __restrict__ Q, const __half* __restrict__ K,
              const __half* __restrict__ V, __half* __restrict__ O)
{
    __shared__ __half sm[2 * 64 * ASTR * 2];   // 36 KB

    int tid  = threadIdx.x;
    int lane = tid & 31;
    int w    = tid >> 5;           // 0..7
    int q0   = blockIdx.x * 128;
    int bh   = blockIdx.y;

    const __half* qb = Q + (size_t)bh * Ssz * 64;
    const __half* kb = K + (size_t)bh * Ssz * 64;
    const __half* vb = V + (size_t)bh * Ssz * 64;

    // ---- stage Q (pre-scaled in weights), build fragments, free smem ----
    #pragma unroll
    for (int i = 0; i < 4; i++) {
        int c = tid + i * 256;
        int row = c >> 3, ch = (c & 7) << 3;
        *(uint4*)&sm[row * ASTR + ch] =
            *(const uint4*)(qb + (size_t)(q0 + row) * 64 + ch);
    }
    __syncthreads();

    unsigned qa[4][4];             // 16 rows per warp, 4 k16 chunks
    #pragma unroll
    for (int k16 = 0; k16 < 4; k16++)
        ldmx4(qa[k16],
              sptr(&sm[(w * 16 + (lane & 15)) * ASTR +
                       k16 * 16 + ((lane >> 4) << 3)]));
    __syncthreads();

    __half* sK = sm;
    __half* sV = sm + 2 * 64 * ASTR;

    // prologue: K group, then V group (512 16B-chunks each; 2/thread)
    #pragma unroll
    for (int i = 0; i < 2; i++) {
        int c = tid + i * 256;
        int row = c >> 3, ch = (c & 7) << 3;
        cp16(sptr(&sK[row * ASTR + ch]), kb + (size_t)row * 64 + ch);
    }
    CP_COMMIT();
    #pragma unroll
    for (int i = 0; i < 2; i++) {
        int c = tid + i * 256;
        int row = c >> 3, ch = (c & 7) << 3;
        cp16(sptr(&sV[row * ASTR + ch]), vb + (size_t)row * 64 + ch);
    }
    CP_COMMIT();

    float liA = 0.f, liB = 0.f;
    float of[8][4] = {};

    #pragma unroll 1
    for (int kt = 0; kt < 64; kt++) {
        CP_WAIT1();          // K resident (V may still be in flight)
        __syncthreads();
        if (kt + 1 < 64) {
            int nb = (kt + 1) & 1;
            const __half* kg = kb + (size_t)(kt + 1) * 64 * 64;
            const __half* vg = vb + (size_t)(kt + 1) * 64 * 64;
            #pragma unroll
            for (int i = 0; i < 2; i++) {
                int c = tid + i * 256;
                int row = c >> 3, ch = (c & 7) << 3;
                cp16(sptr(&sK[(nb * 64 + row) * ASTR + ch]), kg + (size_t)row * 64 + ch);
            }
            CP_COMMIT();
            #pragma unroll
            for (int i = 0; i < 2; i++) {
                int c = tid + i * 256;
                int row = c >> 3, ch = (c & 7) << 3;
                cp16(sptr(&sV[(nb * 64 + row) * ASTR + ch]), vg + (size_t)row * 64 + ch);
            }
            CP_COMMIT();
        }
        const __half* cK = sK + (kt & 1) * 64 * ASTR;
        const __half* cV = sV + (kt & 1) * 64 * ASTR;

        // ---- S = Q @ K^T (16 rows x 64 kv per warp) ----
        PU P;
        #pragma unroll
        for (int nt = 0; nt < 8; nt++)
            #pragma unroll
            for (int jj = 0; jj < 4; jj++) P.f[nt][jj] = 0.f;

        #pragma unroll
        for (int k16 = 0; k16 < 4; k16++) {
            #pragma unroll
            for (int ntp = 0; ntp < 4; ntp++) {
                unsigned bb[4];
                ldmx4(bb, sptr(&cK[(ntp * 16 + ((lane >> 4) << 3) + (lane & 7)) * ASTR +
                                   k16 * 16 + (((lane >> 3) & 1) << 3)]));
                mma16816(P.f[2 * ntp],     qa[k16], bb);
                mma16816(P.f[2 * ntp + 1], qa[k16], bb + 2);
            }
        }

        // ---- softmax numerators, pack P in place ----
        {
            float rsA = 0.f, rsB = 0.f;
            #pragma unroll
            for (int nt = 0; nt < 8; nt++) {
                float e0 = ex2(P.f[nt][0]);
                float e1 = ex2(P.f[nt][1]);
                float e2 = ex2(P.f[nt][2]);
                float e3 = ex2(P.f[nt][3]);
                rsA += e0 + e1;
                rsB += e2 + e3;
                P.u[4 * nt]     = packh2(e0, e1);
                P.u[4 * nt + 1] = packh2(e2, e3);
            }
            rsA += __shfl_xor_sync(0xffffffffu, rsA, 1);
            rsA += __shfl_xor_sync(0xffffffffu, rsA, 2);
            rsB += __shfl_xor_sync(0xffffffffu, rsB, 1);
            rsB += __shfl_xor_sync(0xffffffffu, rsB, 2);
            liA += rsA;
            liB += rsB;
        }

        // ---- now require V ----
        if (kt + 1 < 64) { CP_WAIT2(); } else { CP_WAIT0(); }

        // ---- O += P @ V ----
        #pragma unroll
        for (int ntp = 0; ntp < 4; ntp++) {
            #pragma unroll
            for (int kt2 = 0; kt2 < 4; kt2++) {
                unsigned vv[4];
                ldmx4t(vv, sptr(&cV[(kt2 * 16 + (((lane >> 3) & 1) << 3) + (lane & 7)) * ASTR +
                                    ntp * 16 + ((lane >> 4) << 3)]));
                unsigned f0[4] = { P.u[8 * kt2], P.u[8 * kt2 + 1],
                                   P.u[8 * kt2 + 4], P.u[8 * kt2 + 5] };
                mma16816(of[2 * ntp],     f0, vv);
                mma16816(of[2 * ntp + 1], f0, vv + 2);
            }
        }
    }

    // ---- epilogue ----
    int b = bh / NHsz, h = bh % NHsz;
    float invA = 1.0f / liA, invB = 1.0f / liB;
    int rg = q0 + w * 16 + (lane >> 2);
    #pragma unroll
    for (int ntd = 0; ntd < 8; ntd++) {
        int c = h * 64 + ntd * 8 + ((lane & 3) << 1);
        *(__half2*)&O[((size_t)(b * Ssz + rg)) * Esz + c] =
            __floats2half2_rn(of[ntd][0] * invA, of[ntd][1] * invA);
        *(__half2*)&O[((size_t)(b * Ssz + rg + 8)) * Esz + c] =
            __floats2half2_rn(of[ntd][2] * invB, of[ntd][3] * invB);
    }
}

// ---------------------------------------------------------------------------
// launch
// ---------------------------------------------------------------------------
extern "C" void kernel_launch(void* const* d_in, const int* in_sizes, int n_in,
                              void* d_out, int out_size)
{
    const float* x     = (const float*)d_in[0];
    const float* cond  = (const float*)d_in[1];
    const float* ln1w  = (const float*)d_in[14];
    const float* ln1b  = (const float*)d_in[15];
    const float* ln2w  = (const float*)d_in[16];
    const float* ln2b  = (const float*)d_in[17];
    const float* wq    = (const float*)d_in[18];
    const float* wk    = (const float*)d_in[19];
    const float* wv    = (const float*)d_in[20];
    const float* wo    = (const float*)d_in[21];
    const float* ff1w  = (const float*)d_in[22];
    const float* ff1b  = (const float*)d_in[23];
    const float* ff2w  = (const float*)d_in[24];
    const float* ff2b  = (const float*)d_in[25];

    float *mods, *y;
    __half *wqkvh, *woh, *ff1h, *ff2h, *y1h, *qkv, *atth, *z1h, *hh;
    cudaGetSymbolAddress((void**)&mods,  g_mods);
    cudaGetSymbolAddress((void**)&wqkvh, g_wqkvh);
    cudaGetSymbolAddress((void**)&woh,   g_woh);
    cudaGetSymbolAddress((void**)&ff1h,  g_ff1h);
    cudaGetSymbolAddress((void**)&ff2h,  g_ff2h);
    cudaGetSymbolAddress((void**)&y1h,   g_y1h);
    cudaGetSymbolAddress((void**)&qkv,   g_qkv);
    cudaGetSymbolAddress((void**)&atth,  g_atth);
    cudaGetSymbolAddress((void**)&y,     g_y);
    cudaGetSymbolAddress((void**)&z1h,   g_z1h);
    cudaGetSymbolAddress((void**)&hh,    g_hh);

    CondPtrs cp;
    cp.w[0] = (const float*)d_in[2];  cp.b[0] = (const float*)d_in[3];
    cp.w[1] = (const float*)d_in[4];  cp.b[1] = (const float*)d_in[5];
    cp.w[2] = (const float*)d_in[6];  cp.b[2] = (const float*)d_in[7];
    cp.w[3] = (const float*)d_in[8];  cp.b[3] = (const float*)d_in[9];
    cp.w[4] = (const float*)d_in[10]; cp.b[4] = (const float*)d_in[11];
    cp.w[5] = (const float*)d_in[12]; cp.b[5] = (const float*)d_in[13];

    // merged weight conversion; Wq carries 0.125*log2(e) for EX2 softmax
    const float QSCL = 0.125f * 1.4426950408889634f;
    CvtJobs cj;
    cj.W[0] = wq;   cj.Wt[0] = wqkvh;                 cj.K[0] = Esz;  cj.N[0] = Esz;  cj.scl[0] = QSCL;
    cj.W[1] = wk;   cj.Wt[1] = wqkvh + Esz * Esz;     cj.K[1] = Esz;  cj.N[1] = Esz;  cj.scl[1] = 1.f;
    cj.W[2] = wv;   cj.Wt[2] = wqkvh + 2 * Esz * Esz; cj.K[2] = Esz;  cj.N[2] = Esz;  cj.scl[2] = 1.f;
    cj.W[3] = wo;   cj.Wt[3] = woh;                   cj.K[3] = Esz;  cj.N[3] = Esz;  cj.scl[3] = 1.f;
    cj.W[4] = ff1w; cj.Wt[4] = ff1h;                  cj.K[4] = Esz;  cj.N[4] = FFsz; cj.scl[4] = 1.f;
    cj.W[5] = ff2w; cj.Wt[5] = ff2h;                  cj.K[5] = FFsz; cj.N[5] = Esz;  cj.scl[5] = 1.f;
    int nb = 0;
    for (int i = 0; i < 6; i++) { cj.b0[i] = nb; nb += (cj.K[i] >> 5) * (cj.N[i] >> 5); }
    convert_all_k<<<nb, 256>>>(cj);

    const int MODS = Bsz * Esz;

    cond_proj_k<<<dim3(6, Bsz), 384>>>(cond, cp, mods);

    // LN1 + modulate -> fp16
    ln_mod_k<<<ROWS, 128>>>(x, ln1w, ln1b, mods + 0 * MODS, mods + 1 * MODS, y1h);

    // fused QKV GEMM (N=1152), head-major scatter
    hgemm_k<EPI_QKV><<<dim3(ROWS / 128, QKVN / 128), 256>>>(y1h, wqkvh, nullptr, qkv, QKVN, Esz, nullptr, nullptr);

    // flash attention (256 threads / 8 warps)
    attn_h_k<<<dim3(Ssz / 128, Bsz * NHsz), 256>>>(qkv, qkv + HEADSZ, qkv + 2 * HEADSZ, atth);

    // Wo + alpha1 + residual -> y (fp32)
    hgemm_k<EPI_WO><<<dim3(ROWS / 128, Esz / 128), 256>>>(atth, woh, nullptr, y, Esz, Esz, x, mods + 2 * MODS);

    // LN2 + modulate -> fp16
    ln_mod_k<<<ROWS, 128>>>(y, ln2w, ln2b, mods + 3 * MODS, mods + 4 * MODS, z1h);

    // FF1 + relu -> fp16
    hgemm_k<EPI_FF1><<<dim3(ROWS / 128, FFsz / 128), 256>>>(z1h, ff1h, ff1b, hh, FFsz, Esz, nullptr, nullptr);

    // FF2 + alpha2 + residual -> out (fp32)
    hgemm_k<EPI_FF2><<<dim3(ROWS / 128, Esz / 128), 256>>>(hh, ff2h, ff2b, (float*)d_out, Esz, FFsz, y, mods + 5 * MODS);
}

// round 15
// speedup vs baseline: 1.1211x; 1.1211x over previous
#include <cuda_runtime.h>
#include <cuda_fp16.h>
#include <cuda_bf16.h>
#include <cstddef>

// ---------------------------------------------------------------------------
// DiT block, fp16 mma.sync + ldmatrix.x4 + cp.async.
// Attention: R9 config (128 thr, 4 warps x 32 q-rows, shared K/V frags,
//            split K/V cp.async groups, EX2 softmax, in-place P pack).
// GEMM: BK=64 (6 iters for K=384), 72KB dynamic smem, 2 CTAs/SM.
// B=4, S=4096, E=384, NH=6, HD=64, FF=1536.
// ---------------------------------------------------------------------------

#define Bsz   4
#define Ssz   4096
#define Esz   384
#define NHsz  6
#define HDsz  64
#define FFsz  1536
#define ROWS  (Bsz * Ssz)          // 16384
#define QKVN  (3 * Esz)            // 1152
#define HEADSZ ((size_t)Bsz * NHsz * Ssz * HDsz)

// ---------------- scratch ----------------
__device__ float  g_mods [6 * Bsz * Esz];
__device__ __half g_wqkvh[QKVN * Esz];    // [N=1152][K=384]
__device__ __half g_woh  [Esz * Esz];
__device__ __half g_ff1h [FFsz * Esz];    // [N=1536][K=384]
__device__ __half g_ff2h [Esz * FFsz];    // [N=384][K=1536]
__device__ __half g_y1h  [ROWS * Esz];
__device__ __half g_qkv  [3 * Bsz * NHsz * Ssz * HDsz];
__device__ __half g_atth [ROWS * Esz];
__device__ float  g_y    [ROWS * Esz];
__device__ __half g_z1h  [ROWS * Esz];
__device__ __half g_hh   [ROWS * FFsz];

// ---------------- PTX helpers ----------------
__device__ __forceinline__ void mma16816(float* c, const unsigned* a, const unsigned* b)
{
    asm volatile(
        "mma.sync.aligned.m16n8k16.row.col.f32.f16.f16.f32 "
        "{%0,%1,%2,%3},{%4,%5,%6,%7},{%8,%9},{%0,%1,%2,%3};"
        : "+f"(c[0]), "+f"(c[1]), "+f"(c[2]), "+f"(c[3])
        : "r"(a[0]), "r"(a[1]), "r"(a[2]), "r"(a[3]), "r"(b[0]), "r"(b[1]));
}
__device__ __forceinline__ unsigned packh2(float a, float b)
{
    __half2 h = __floats2half2_rn(a, b);
    return *(unsigned*)&h;
}
__device__ __forceinline__ float ex2(float x)
{
    float r;
    asm("ex2.approx.f32 %0, %1;" : "=f"(r) : "f"(x));
    return r;
}
__device__ __forceinline__ unsigned sptr(const void* p)
{
    return (unsigned)__cvta_generic_to_shared(p);
}
__device__ __forceinline__ void ldmx4(unsigned* r, unsigned addr)
{
    asm volatile("ldmatrix.sync.aligned.m8n8.x4.shared.b16 {%0,%1,%2,%3},[%4];"
                 : "=r"(r[0]), "=r"(r[1]), "=r"(r[2]), "=r"(r[3]) : "r"(addr));
}
__device__ __forceinline__ void ldmx4t(unsigned* r, unsigned addr)
{
    asm volatile("ldmatrix.sync.aligned.m8n8.x4.trans.shared.b16 {%0,%1,%2,%3},[%4];"
                 : "=r"(r[0]), "=r"(r[1]), "=r"(r[2]), "=r"(r[3]) : "r"(addr));
}
__device__ __forceinline__ void cp16(unsigned dst, const void* src)
{
    asm volatile("cp.async.cg.shared.global [%0],[%1],16;" :: "r"(dst), "l"(src));
}
#define CP_COMMIT() asm volatile("cp.async.commit_group;")
#define CP_WAIT0()  asm volatile("cp.async.wait_group 0;")
#define CP_WAIT1()  asm volatile("cp.async.wait_group 1;")
#define CP_WAIT2()  asm volatile("cp.async.wait_group 2;")

// ---------------------------------------------------------------------------
// 0) merged weight convert (+ per-job scale): W[K][N] fp32 -> Wt[N][K] fp16
// ---------------------------------------------------------------------------
struct CvtJobs {
    const float* W[6];
    __half*      Wt[6];
    float scl[6];
    int K[6], N[6], b0[6];
};

__global__ __launch_bounds__(256)
void convert_all_k(CvtJobs j)
{
    __shared__ float t[32][33];
    int bid = blockIdx.x;
    int ji = 0;
    #pragma unroll
    for (int i = 1; i < 6; i++) if (bid >= j.b0[i]) ji = i;
    int tile = bid - j.b0[ji];
    int K = j.K[ji], N = j.N[ji];
    int nkt = K >> 5;
    int k0 = (tile % nkt) << 5, n0 = (tile / nkt) << 5;
    float scl = j.scl[ji];

    const float* W  = j.W[ji];
    __half*      Wt = j.Wt[ji];
    int tx = threadIdx.x & 31, ty = threadIdx.x >> 5;
    #pragma unroll
    for (int i = 0; i < 32; i += 8)
        t[ty + i][tx] = W[(size_t)(k0 + ty + i) * N + n0 + tx];
    __syncthreads();
    #pragma unroll
    for (int i = 0; i < 32; i += 8)
        Wt[(size_t)(n0 + ty + i) * K + k0 + tx] = __float2half(t[tx][ty + i] * scl);
}

// ---------------------------------------------------------------------------
// 1) cond projections
// ---------------------------------------------------------------------------
struct CondPtrs { const float* w[6]; const float* b[6]; };

__global__ __launch_bounds__(384)
void cond_proj_k(const float* __restrict__ cond, CondPtrs p, float* __restrict__ mods)
{
    __shared__ float cs[Esz];
    int n  = threadIdx.x;
    int pi = blockIdx.x;
    int b  = blockIdx.y;
    cs[n] = cond[b * Esz + n];
    __syncthreads();
    const float* W = p.w[pi];
    float acc = p.b[pi][n];
    #pragma unroll 4
    for (int k = 0; k < Esz; k++)
        acc += cs[k] * W[k * Esz + n];
    mods[(pi * Bsz + b) * Esz + n] = acc;
}

// ---------------------------------------------------------------------------
// 2) fused LayerNorm + AdaLN modulation -> fp16
// ---------------------------------------------------------------------------
__global__ __launch_bounds__(128)
void ln_mod_k(const float* __restrict__ X,
              const float* __restrict__ lw, const float* __restrict__ lb,
              const float* __restrict__ gamma, const float* __restrict__ beta,
              __half* __restrict__ Y)
{
    __shared__ float sb1[4], sb2[4];
    int row = blockIdx.x;
    int b   = row >> 12;
    const float* x = X + (size_t)row * Esz;
    int t = threadIdx.x;

    float v0 = x[t], v1 = x[t + 128], v2 = x[t + 256];
    float s = v0 + v1 + v2;
    #pragma unroll
    for (int m = 16; m >= 1; m >>= 1) s += __shfl_xor_sync(0xffffffffu, s, m);
    if ((t & 31) == 0) sb1[t >> 5] = s;
    __syncthreads();
    float mean = (sb1[0] + sb1[1] + sb1[2] + sb1[3]) * (1.0f / Esz);

    float d0 = v0 - mean, d1 = v1 - mean, d2 = v2 - mean;
    float sq = d0 * d0 + d1 * d1 + d2 * d2;
    #pragma unroll
    for (int m = 16; m >= 1; m >>= 1) sq += __shfl_xor_sync(0xffffffffu, sq, m);
    if ((t & 31) == 0) sb2[t >> 5] = sq;
    __syncthreads();
    float var  = (sb2[0] + sb2[1] + sb2[2] + sb2[3]) * (1.0f / Esz);
    float rinv = rsqrtf(var + 1e-5f);

    __half* y = Y + (size_t)row * Esz;
    const float* gm = gamma + b * Esz;
    const float* bt = beta  + b * Esz;
    #pragma unroll
    for (int c = 0; c < 3; c++) {
        int   idx = t + c * 128;
        float d   = (c == 0 ? d0 : (c == 1 ? d1 : d2));
        float ln  = d * rinv * lw[idx] + lb[idx];
        y[idx] = __float2half(ln * (1.0f + gm[idx]) + bt[idx]);
    }
}

// ---------------------------------------------------------------------------
// 3) fp16 GEMM, block 128x128, BK=64, 8 warps (4m x 2n), warp 32x64.
//    72KB dynamic smem (stride 72, ldmatrix conflict-free), cp.async
//    double buffer, halved barrier count vs BK=32.
// ---------------------------------------------------------------------------
enum { EPI_QKV = 0, EPI_WO = 1, EPI_FF1 = 2, EPI_FF2 = 3 };

#define GSTR 72
#define GTILE (128 * GSTR)     // halfs per buffer per array
#define GSMEM (4 * GTILE * sizeof(__half))   // 73728 B

template <int EPI>
__global__ __launch_bounds__(256)
void hgemm_k(const __half* __restrict__ A, const __half* __restrict__ Wt,
             const float* __restrict__ bias, void* __restrict__ Cout,
             int N, int K,
             const float* __restrict__ resid, const float* __restrict__ alpha)
{
    extern __shared__ __half dsm[];
    __half* As = dsm;               // [2][128][GSTR]
    __half* Ws = dsm + 2 * GTILE;   // [2][128][GSTR]

    int tid  = threadIdx.x;
    int lane = tid & 31;
    int wid  = tid >> 5;
    int wm   = wid & 3;
    int wn   = wid >> 2;
    int bm   = blockIdx.x * 128;
    int bn   = blockIdx.y * 128;

    float acc[2][8][4] = {};

    // prefetch stage 0: 128 rows x 8 chunks(16B) per array -> 4 cp16/thread/array
    #pragma unroll
    for (int i = 0; i < 4; i++) {
        int c = tid + i * 256;
        int row = c >> 3, ch = (c & 7) << 3;
        cp16(sptr(&As[row * GSTR + ch]), A  + (size_t)(bm + row) * K + ch);
        cp16(sptr(&Ws[row * GSTR + ch]), Wt + (size_t)(bn + row) * K + ch);
    }
    CP_COMMIT();

    int nit = K >> 6;
    #pragma unroll 1
    for (int it = 0; it < nit; it++) {
        CP_WAIT0();
        __syncthreads();
        if (it + 1 < nit) {
            int k0 = (it + 1) << 6;
            int nb = (it + 1) & 1;
            #pragma unroll
            for (int i = 0; i < 4; i++) {
                int c = tid + i * 256;
                int row = c >> 3, ch = (c & 7) << 3;
                cp16(sptr(&As[(nb * 128 + row) * GSTR + ch]),
                     A + (size_t)(bm + row) * K + k0 + ch);
                cp16(sptr(&Ws[(nb * 128 + row) * GSTR + ch]),
                     Wt + (size_t)(bn + row) * K + k0 + ch);
            }
            CP_COMMIT();
        }
        const __half* cA = As + (it & 1) * GTILE;
        const __half* cW = Ws + (it & 1) * GTILE;

        #pragma unroll
        for (int ks = 0; ks < 4; ks++) {
            int c0 = ks * 16;
            unsigned a[2][4], b[8][2];
            #pragma unroll
            for (int mt = 0; mt < 2; mt++)
                ldmx4(a[mt], sptr(&cA[(wm * 32 + mt * 16 + (lane & 15)) * GSTR +
                                      c0 + ((lane >> 4) << 3)]));
            #pragma unroll
            for (int ntp = 0; ntp < 4; ntp++) {
                unsigned bb[4];
                ldmx4(bb, sptr(&cW[(wn * 64 + ntp * 16 + ((lane >> 4) << 3) + (lane & 7)) * GSTR +
                                   c0 + (((lane >> 3) & 1) << 3)]));
                b[2 * ntp][0]     = bb[0]; b[2 * ntp][1]     = bb[1];
                b[2 * ntp + 1][0] = bb[2]; b[2 * ntp + 1][1] = bb[3];
            }
            #pragma unroll
            for (int mt = 0; mt < 2; mt++)
                #pragma unroll
                for (int nt = 0; nt < 8; nt++)
                    mma16816(acc[mt][nt], a[mt], b[nt]);
        }
    }

    // ---- epilogue ----
    #pragma unroll
    for (int mt = 0; mt < 2; mt++) {
        int r = bm + wm * 32 + mt * 16 + (lane >> 2);
        #pragma unroll
        for (int nt = 0; nt < 8; nt++) {
            int c = bn + wn * 64 + nt * 8 + ((lane & 3) << 1);
            float* ac = acc[mt][nt];

            if (EPI == EPI_QKV) {
                __half* C = (__half*)Cout;
                int which = c / Esz, cc = c % Esz;
                int h = cc >> 6, d = cc & 63;
                #pragma unroll
                for (int rr = 0; rr < 2; rr++) {
                    int m = r + rr * 8, b = m >> 12, s = m & 4095;
                    __half2 v = __floats2half2_rn(ac[rr * 2], ac[rr * 2 + 1]);
                    size_t idx = ((((size_t)which * Bsz + b) * NHsz + h) * Ssz + s);
                    *(__half2*)&C[(idx << 6) + d] = v;
                }
            } else if (EPI == EPI_FF1) {
                __half* C = (__half*)Cout;
                float b0 = bias[c], b1 = bias[c + 1];
                #pragma unroll
                for (int rr = 0; rr < 2; rr++) {
                    int m = r + rr * 8;
                    float t0 = ac[rr * 2] + b0;     t0 = t0 > 0.f ? t0 : 0.f;
                    float t1 = ac[rr * 2 + 1] + b1; t1 = t1 > 0.f ? t1 : 0.f;
                    *(__half2*)&C[(size_t)m * N + c] = __floats2half2_rn(t0, t1);
                }
            } else {
                float* C = (float*)Cout;
                float b0 = 0.f, b1 = 0.f;
                if (EPI == EPI_FF2) { b0 = bias[c]; b1 = bias[c + 1]; }
                #pragma unroll
                for (int rr = 0; rr < 2; rr++) {
                    int m = r + rr * 8, bb = m >> 12;
                    float2 al = *(const float2*)&alpha[bb * Esz + c];
                    float2 rs = *(const float2*)&resid[(size_t)m * Esz + c];
                    float2 v;
                    v.x = rs.x + (ac[rr * 2] + b0) * al.x;
                    v.y = rs.y + (ac[rr * 2 + 1] + b1) * al.y;
                    *(float2*)&C[(size_t)m * Esz + c] = v;
                }
            }
        }
    }
}

// ---------------------------------------------------------------------------
// 4) fp16 flash attention — R9 config (banked 658us): 128 threads, 4 warps
//    x 32 q-rows (2 m-tiles share K/V frags), KV tile 64, split cp.async
//    groups, EX2 softmax, in-place P pack. 36 KB static smem.
// ---------------------------------------------------------------------------
#define ASTR 72

union PU { float f[8][4]; unsigned u[32]; };

__global__ __launch_bounds__(128)
void attn_h_k(const __half* __restrict__ Q, const __half* __restrict__ K,
              const __half* __restrict__ V, __half* __restrict__ O)
{
    __shared__ __half sm[2 * 64 * ASTR * 2];   // 36 KB

    int tid  = threadIdx.x;
    int lane = tid & 31;
    int w    = tid >> 5;
    int q0   = blockIdx.x * 128;
    int bh   = blockIdx.y;

    const __half* qb = Q + (size_t)bh * Ssz * 64;
    const __half* kb = K + (size_t)bh * Ssz * 64;
    const __half* vb = V + (size_t)bh * Ssz * 64;

    // ---- stage Q (pre-scaled in weights), build fragments, free smem ----
    #pragma unroll
    for (int i = 0; i < 8; i++) {
        int c = tid + i * 128;
        int row = c >> 3, ch = (c & 7) << 3;
        *(uint4*)&sm[row * ASTR + ch] =
            *(const uint4*)(qb + (size_t)(q0 + row) * 64 + ch);
    }
    __syncthreads();

    unsigned qa[2][4][4];
    #pragma unroll
    for (int mt = 0; mt < 2; mt++)
        #pragma unroll
        for (int k16 = 0; k16 < 4; k16++)
            ldmx4(qa[mt][k16],
                  sptr(&sm[(w * 32 + mt * 16 + (lane & 15)) * ASTR +
                           k16 * 16 + ((lane >> 4) << 3)]));
    __syncthreads();

    __half* sK = sm;
    __half* sV = sm + 2 * 64 * ASTR;

    // prologue: K group, then V group
    #pragma unroll
    for (int i = 0; i < 4; i++) {
        int c = tid + i * 128;
        int row = c >> 3, ch = (c & 7) << 3;
        cp16(sptr(&sK[row * ASTR + ch]), kb + (size_t)row * 64 + ch);
    }
    CP_COMMIT();
    #pragma unroll
    for (int i = 0; i < 4; i++) {
        int c = tid + i * 128;
        int row = c >> 3, ch = (c & 7) << 3;
        cp16(sptr(&sV[row * ASTR + ch]), vb + (size_t)row * 64 + ch);
    }
    CP_COMMIT();

    float li[2][2] = {};
    float of[2][8][4] = {};

    #pragma unroll 1
    for (int kt = 0; kt < 64; kt++) {
        CP_WAIT1();          // current K resident (V may still be in flight)
        __syncthreads();
        if (kt + 1 < 64) {
            int nb = (kt + 1) & 1;
            const __half* kg = kb + (size_t)(kt + 1) * 64 * 64;
            const __half* vg = vb + (size_t)(kt + 1) * 64 * 64;
            #pragma unroll
            for (int i = 0; i < 4; i++) {
                int c = tid + i * 128;
                int row = c >> 3, ch = (c & 7) << 3;
                cp16(sptr(&sK[(nb * 64 + row) * ASTR + ch]), kg + (size_t)row * 64 + ch);
            }
            CP_COMMIT();
            #pragma unroll
            for (int i = 0; i < 4; i++) {
                int c = tid + i * 128;
                int row = c >> 3, ch = (c & 7) << 3;
                cp16(sptr(&sV[(nb * 64 + row) * ASTR + ch]), vg + (size_t)row * 64 + ch);
            }
            CP_COMMIT();
        }
        const __half* cK = sK + (kt & 1) * 64 * ASTR;
        const __half* cV = sV + (kt & 1) * 64 * ASTR;

        // ---- S = Q @ K^T ----
        PU P0, P1;
        #pragma unroll
        for (int nt = 0; nt < 8; nt++)
            #pragma unroll
            for (int jj = 0; jj < 4; jj++) { P0.f[nt][jj] = 0.f; P1.f[nt][jj] = 0.f; }

        #pragma unroll
        for (int k16 = 0; k16 < 4; k16++) {
            #pragma unroll
            for (int ntp = 0; ntp < 4; ntp++) {
                unsigned bb[4];
                ldmx4(bb, sptr(&cK[(ntp * 16 + ((lane >> 4) << 3) + (lane & 7)) * ASTR +
                                   k16 * 16 + (((lane >> 3) & 1) << 3)]));
                mma16816(P0.f[2 * ntp],     qa[0][k16], bb);
                mma16816(P0.f[2 * ntp + 1], qa[0][k16], bb + 2);
                mma16816(P1.f[2 * ntp],     qa[1][k16], bb);
                mma16816(P1.f[2 * ntp + 1], qa[1][k16], bb + 2);
            }
        }

        // ---- softmax numerators (single EX2 each), pack P in place ----
        #pragma unroll
        for (int mt = 0; mt < 2; mt++) {
            PU* P = mt ? &P1 : &P0;
            float rsA = 0.f, rsB = 0.f;
            #pragma unroll
            for (int nt = 0; nt < 8; nt++) {
                float e0 = ex2(P->f[nt][0]);
                float e1 = ex2(P->f[nt][1]);
                float e2 = ex2(P->f[nt][2]);
                float e3 = ex2(P->f[nt][3]);
                rsA += e0 + e1;
                rsB += e2 + e3;
                P->u[4 * nt]     = packh2(e0, e1);
                P->u[4 * nt + 1] = packh2(e2, e3);
            }
            rsA += __shfl_xor_sync(0xffffffffu, rsA, 1);
            rsA += __shfl_xor_sync(0xffffffffu, rsA, 2);
            rsB += __shfl_xor_sync(0xffffffffu, rsB, 1);
            rsB += __shfl_xor_sync(0xffffffffu, rsB, 2);
            li[mt][0] += rsA;
            li[mt][1] += rsB;
        }

        // ---- now require V (it had S + softmax time to land) ----
        if (kt + 1 < 64) { CP_WAIT2(); } else { CP_WAIT0(); }

        // ---- O += P @ V (shared V fragments for both m-tiles) ----
        #pragma unroll
        for (int ntp = 0; ntp < 4; ntp++) {
            #pragma unroll
            for (int kt2 = 0; kt2 < 4; kt2++) {
                unsigned vv[4];
                ldmx4t(vv, sptr(&cV[(kt2 * 16 + (((lane >> 3) & 1) << 3) + (lane & 7)) * ASTR +
                                    ntp * 16 + ((lane >> 4) << 3)]));
                unsigned f0[4] = { P0.u[8 * kt2], P0.u[8 * kt2 + 1],
                                   P0.u[8 * kt2 + 4], P0.u[8 * kt2 + 5] };
                unsigned f1[4] = { P1.u[8 * kt2], P1.u[8 * kt2 + 1],
                                   P1.u[8 * kt2 + 4], P1.u[8 * kt2 + 5] };
                mma16816(of[0][2 * ntp],     f0, vv);
                mma16816(of[0][2 * ntp + 1], f0, vv + 2);
                mma16816(of[1][2 * ntp],     f1, vv);
                mma16816(of[1][2 * ntp + 1], f1, vv + 2);
            }
        }
    }

    // ---- epilogue ----
    int b = bh / NHsz, h = bh % NHsz;
    #pragma unroll
    for (int mt = 0; mt < 2; mt++) {
        float inv0 = 1.0f / li[mt][0], inv1 = 1.0f / li[mt][1];
        int rg = q0 + w * 32 + mt * 16 + (lane >> 2);
        #pragma unroll
        for (int ntd = 0; ntd < 8; ntd++) {
            int c = h * 64 + ntd * 8 + ((lane & 3) << 1);
            *(__half2*)&O[((size_t)(b * Ssz + rg)) * Esz + c] =
                __floats2half2_rn(of[mt][ntd][0] * inv0, of[mt][ntd][1] * inv0);
            *(__half2*)&O[((size_t)(b * Ssz + rg + 8)) * Esz + c] =
                __floats2half2_rn(of[mt][ntd][2] * inv1, of[mt][ntd][3] * inv1);
        }
    }
}

// ---------------------------------------------------------------------------
// launch
// ---------------------------------------------------------------------------
extern "C" void kernel_launch(void* const* d_in, const int* in_sizes, int n_in,
                              void* d_out, int out_size)
{
    const float* x     = (const float*)d_in[0];
    const float* cond  = (const float*)d_in[1];
    const float* ln1w  = (const float*)d_in[14];
    const float* ln1b  = (const float*)d_in[15];
    const float* ln2w  = (const float*)d_in[16];
    const float* ln2b  = (const float*)d_in[17];
    const float* wq    = (const float*)d_in[18];
    const float* wk    = (const float*)d_in[19];
    const float* wv    = (const float*)d_in[20];
    const float* wo    = (const float*)d_in[21];
    const float* ff1w  = (const float*)d_in[22];
    const float* ff1b  = (const float*)d_in[23];
    const float* ff2w  = (const float*)d_in[24];
    const float* ff2b  = (const float*)d_in[25];

    float *mods, *y;
    __half *wqkvh, *woh, *ff1h, *ff2h, *y1h, *qkv, *atth, *z1h, *hh;
    cudaGetSymbolAddress((void**)&mods,  g_mods);
    cudaGetSymbolAddress((void**)&wqkvh, g_wqkvh);
    cudaGetSymbolAddress((void**)&woh,   g_woh);
    cudaGetSymbolAddress((void**)&ff1h,  g_ff1h);
    cudaGetSymbolAddress((void**)&ff2h,  g_ff2h);
    cudaGetSymbolAddress((void**)&y1h,   g_y1h);
    cudaGetSymbolAddress((void**)&qkv,   g_qkv);
    cudaGetSymbolAddress((void**)&atth,  g_atth);
    cudaGetSymbolAddress((void**)&y,     g_y);
    cudaGetSymbolAddress((void**)&z1h,   g_z1h);
    cudaGetSymbolAddress((void**)&hh,    g_hh);

    CondPtrs cp;
    cp.w[0] = (const float*)d_in[2];  cp.b[0] = (const float*)d_in[3];
    cp.w[1] = (const float*)d_in[4];  cp.b[1] = (const float*)d_in[5];
    cp.w[2] = (const float*)d_in[6];  cp.b[2] = (const float*)d_in[7];
    cp.w[3] = (const float*)d_in[8];  cp.b[3] = (const float*)d_in[9];
    cp.w[4] = (const float*)d_in[10]; cp.b[4] = (const float*)d_in[11];
    cp.w[5] = (const float*)d_in[12]; cp.b[5] = (const float*)d_in[13];

    // raise dynamic-smem cap for the GEMM instantiations (72KB)
    static bool attr_done = false;
    if (!attr_done) {
        cudaFuncSetAttribute(hgemm_k<EPI_QKV>, cudaFuncAttributeMaxDynamicSharedMemorySize, (int)GSMEM);
        cudaFuncSetAttribute(hgemm_k<EPI_WO>,  cudaFuncAttributeMaxDynamicSharedMemorySize, (int)GSMEM);
        cudaFuncSetAttribute(hgemm_k<EPI_FF1>, cudaFuncAttributeMaxDynamicSharedMemorySize, (int)GSMEM);
        cudaFuncSetAttribute(hgemm_k<EPI_FF2>, cudaFuncAttributeMaxDynamicSharedMemorySize, (int)GSMEM);
        attr_done = true;
    }

    // merged weight conversion; Wq carries 0.125*log2(e) for EX2 softmax
    const float QSCL = 0.125f * 1.4426950408889634f;
    CvtJobs cj;
    cj.W[0] = wq;   cj.Wt[0] = wqkvh;                 cj.K[0] = Esz;  cj.N[0] = Esz;  cj.scl[0] = QSCL;
    cj.W[1] = wk;   cj.Wt[1] = wqkvh + Esz * Esz;     cj.K[1] = Esz;  cj.N[1] = Esz;  cj.scl[1] = 1.f;
    cj.W[2] = wv;   cj.Wt[2] = wqkvh + 2 * Esz * Esz; cj.K[2] = Esz;  cj.N[2] = Esz;  cj.scl[2] = 1.f;
    cj.W[3] = wo;   cj.Wt[3] = woh;                   cj.K[3] = Esz;  cj.N[3] = Esz;  cj.scl[3] = 1.f;
    cj.W[4] = ff1w; cj.Wt[4] = ff1h;                  cj.K[4] = Esz;  cj.N[4] = FFsz; cj.scl[4] = 1.f;
    cj.W[5] = ff2w; cj.Wt[5] = ff2h;                  cj.K[5] = FFsz; cj.N[5] = Esz;  cj.scl[5] = 1.f;
    int nb = 0;
    for (int i = 0; i < 6; i++) { cj.b0[i] = nb; nb += (cj.K[i] >> 5) * (cj.N[i] >> 5); }
    convert_all_k<<<nb, 256>>>(cj);

    const int MODS = Bsz * Esz;

    cond_proj_k<<<dim3(6, Bsz), 384>>>(cond, cp, mods);

    // LN1 + modulate -> fp16
    ln_mod_k<<<ROWS, 128>>>(x, ln1w, ln1b, mods + 0 * MODS, mods + 1 * MODS, y1h);

    // fused QKV GEMM (N=1152), head-major scatter
    hgemm_k<EPI_QKV><<<dim3(ROWS / 128, QKVN / 128), 256, GSMEM>>>(y1h, wqkvh, nullptr, qkv, QKVN, Esz, nullptr, nullptr);

    // flash attention (128 threads — R9 config)
    attn_h_k<<<dim3(Ssz / 128, Bsz * NHsz), 128>>>(qkv, qkv + HEADSZ, qkv + 2 * HEADSZ, atth);

    // Wo + alpha1 + residual -> y (fp32)
    hgemm_k<EPI_WO><<<dim3(ROWS / 128, Esz / 128), 256, GSMEM>>>(atth, woh, nullptr, y, Esz, Esz, x, mods + 2 * MODS);

    // LN2 + modulate -> fp16
    ln_mod_k<<<ROWS, 128>>>(y, ln2w, ln2b, mods + 3 * MODS, mods + 4 * MODS, z1h);

    // FF1 + relu -> fp16
    hgemm_k<EPI_FF1><<<dim3(ROWS / 128, FFsz / 128), 256, GSMEM>>>(z1h, ff1h, ff1b, hh, FFsz, Esz, nullptr, nullptr);

    // FF2 + alpha2 + residual -> out (fp32)
    hgemm_k<EPI_FF2><<<dim3(ROWS / 128, Esz / 128), 256, GSMEM>>>(hh, ff2h, ff2b, (float*)d_out, Esz, FFsz, y, mods + 5 * MODS);
}